// round 16
// baseline (speedup 1.0000x reference)
#include <cuda_runtime.h>

#define H 1024
#define T 20
#define GRID 128
#define BLK 512

// Scratch (__device__ globals per alloc-free rule). Fully written before read.
__device__ float g_h1[H];        // enc layer1 output at t=0, batch 4095
__device__ float g_d0[T * H];    // dec layer0 outputs, t-major
__device__ unsigned g_cnt = 0;   // barrier arrival counter (self-resets each use)
__device__ unsigned g_gen = 0;   // barrier generation (monotonic; graph-replay safe)
// Dataflow state for phase-2 -> phase-3 handoff (replaces grid barrier 2).
// Chunk c covers d0 channels [128c, 128c+128), produced by blocks [16c, 16c+16).
__device__ unsigned g_flag[8 * 32];   // stride-32 padding: one counter per line
__device__ unsigned g_outrdy;         // d_out initialized flag

__device__ __forceinline__ float warp_reduce(float v) {
#pragma unroll
    for (int o = 16; o; o >>= 1) v += __shfl_xor_sync(0xffffffffu, v, o);
    return v;
}

__device__ __forceinline__ unsigned ld_acquire(const unsigned* p) {
    unsigned v;
    asm volatile("ld.acquire.gpu.global.u32 %0, [%1];" : "=r"(v) : "l"(p));
    return v;
}

// Flat sense-reversal grid barrier (R8-proven; hierarchical was SLOWER).
// GRID=128 <= 148 SMs at 1 block/SM -> co-resident single wave, spin-safe.
__device__ __forceinline__ void grid_barrier() {
    __syncthreads();
    if (threadIdx.x == 0) {
        __threadfence();                                  // release our block's writes
        unsigned gen = *(volatile unsigned*)&g_gen;
        if (atomicAdd(&g_cnt, 1u) == GRID - 1) {
            g_cnt = 0;
            __threadfence();
            atomicAdd(&g_gen, 1u);
        } else {
            while (*(volatile unsigned*)&g_gen == gen) {}
        }
        __threadfence();                                  // acquire others' writes
    }
    __syncthreads();
}

__global__ void __launch_bounds__(BLK, 1) fused_net(
    const float* __restrict__ x,
    const float* __restrict__ enc_w0, const float* __restrict__ enc_b0,
    const float* __restrict__ enc_w1, const float* __restrict__ enc_b1,
    const float* __restrict__ dec_w0, const float* __restrict__ dec_u0,
    const float* __restrict__ dec_b0,
    const float* __restrict__ dec_w1, const float* __restrict__ dec_u1,
    const float* __restrict__ dec_b1,
    const float* __restrict__ out_w, const float* __restrict__ out_b,
    float* __restrict__ out)
{
    __shared__ float s_vec[H];         // staged vector for matvec phases
    __shared__ float s_part[16];       // per-warp partial dot sums
    __shared__ float s_pre[2][8][T];   // dec1 pre-activation partials (K-halves)
    __shared__ float s_d1[8][T];       // dec1 post-scan outputs (for projection)

    const int tid = threadIdx.x;
    const int warp = tid >> 5, lane = tid & 31;
    const int row = warp & 7;          // phases 1/2: row index in block
    const int half = warp >> 3;        // phases 1/2: K-half
    const int h = blockIdx.x * 8 + row;

    // Replay-safe reset of dataflow flags BEFORE barrier 1 (its fences order
    // these zero-stores ahead of any post-barrier arrival/consumer).
    if (tid == 0 && blockIdx.x < 8) g_flag[blockIdx.x * 32] = 0;
    if (tid == 0 && blockIdx.x == 0) g_outrdy = 0;

    // ---- Phase 1 demand loads (critical path).
    float4 wa, wb, wc, wd;
    {
        const float4* w1p = (const float4*)(enc_w1 + (size_t)h * H) + half * 128;
        wa = __ldg(w1p + lane);
        wb = __ldg(w1p + 32 + lane);
        wc = __ldg(w1p + 64 + lane);
        wd = __ldg(w1p + 96 + lane);
    }
    // x: (20, 4096, 2); x[0, 4095, :] at flat {8190, 8191}. h_{-1}=0 => enc_u unused.
    const float x0 = x[8190], x1 = x[8191];
#pragma unroll
    for (int i = tid; i < H; i += BLK) {
        float v = fmaf(enc_w0[2 * i], x0, fmaf(enc_w0[2 * i + 1], x1, enc_b0[i]));
        s_vec[i] = fmaxf(v, 0.0f);
    }

    // ---- Phase 1: h1 = relu(enc_w1 @ relu(enc_w0 @ x + b0) + b1).
    {
        __syncthreads();
        const float4* s4 = (const float4*)s_vec + half * 128;
        float4 v0 = s4[lane], v1 = s4[32 + lane], v2 = s4[64 + lane], v3 = s4[96 + lane];
        float acc = 0.0f;
        acc = fmaf(wa.x, v0.x, acc); acc = fmaf(wa.y, v0.y, acc);
        acc = fmaf(wa.z, v0.z, acc); acc = fmaf(wa.w, v0.w, acc);
        acc = fmaf(wb.x, v1.x, acc); acc = fmaf(wb.y, v1.y, acc);
        acc = fmaf(wb.z, v1.z, acc); acc = fmaf(wb.w, v1.w, acc);
        acc = fmaf(wc.x, v2.x, acc); acc = fmaf(wc.y, v2.y, acc);
        acc = fmaf(wc.z, v2.z, acc); acc = fmaf(wc.w, v2.w, acc);
        acc = fmaf(wd.x, v3.x, acc); acc = fmaf(wd.y, v3.y, acc);
        acc = fmaf(wd.z, v3.z, acc); acc = fmaf(wd.w, v3.w, acc);
        acc = warp_reduce(acc);
        if (lane == 0) s_part[warp] = acc;
    }
    // Preload dec_w0 half-row NOW: its DRAM latency hides under barrier 1.
    {
        const float4* w0p = (const float4*)(dec_w0 + (size_t)h * H) + half * 128;
        wa = __ldg(w0p + lane);
        wb = __ldg(w0p + 32 + lane);
        wc = __ldg(w0p + 64 + lane);
        wd = __ldg(w0p + 96 + lane);
    }
    __syncthreads();
    if (tid < 8)
        g_h1[blockIdx.x * 8 + tid] =
            fmaxf(s_part[tid] + s_part[tid + 8] + enc_b1[blockIdx.x * 8 + tid], 0.0f);
    grid_barrier();   // the ONLY grid barrier

    // d_out init (poisoned each replay): block 0 stores out_b, then releases
    // g_outrdy below (after a block sync). Consumers acquire it pre-atomic.
    if (blockIdx.x == 0 && tid < 2 * T) out[tid] = out_b[tid & 1];

    // Phase-3 warp roles: 16 warps = 2 row-quads x 2 K-halves x 4 t-quarters;
    // 4 rows x 5 t x 512 K per warp.
    const int rq = warp & 1;             // row quad: rows [rq*4, rq*4+4)
    const int kh = (warp >> 1) & 1;      // K-half: [kh*512, +512)
    const int tq = warp >> 2;            // t-quarter: t in [tq*5, +5)
    const int h0 = blockIdx.x * 8 + rq * 4;

    // ---- Phase 2: pre = dec_w0 @ h1 + b; 20-step elementwise IndRNN scan
    //      (time-constant input) -> g_d0. Weights already in registers.
    float4 w16[16];                      // phase-3 weights: [r*4+j], r in 0..3
    {
#pragma unroll
        for (int i = tid; i < H; i += BLK) s_vec[i] = g_h1[i];   // coherent
        __syncthreads();
        // Block 0 releases d_out init (stores above, ordered by the sync).
        if (blockIdx.x == 0 && tid == 0) {
            __threadfence();
            atomicExch(&g_outrdy, 1u);
        }
        const float4* s4 = (const float4*)s_vec + half * 128;
        float4 v0 = s4[lane], v1 = s4[32 + lane], v2 = s4[64 + lane], v3 = s4[96 + lane];
        float acc = 0.0f;
        acc = fmaf(wa.x, v0.x, acc); acc = fmaf(wa.y, v0.y, acc);
        acc = fmaf(wa.z, v0.z, acc); acc = fmaf(wa.w, v0.w, acc);
        acc = fmaf(wb.x, v1.x, acc); acc = fmaf(wb.y, v1.y, acc);
        acc = fmaf(wb.z, v1.z, acc); acc = fmaf(wb.w, v1.w, acc);
        acc = fmaf(wc.x, v2.x, acc); acc = fmaf(wc.y, v2.y, acc);
        acc = fmaf(wc.z, v2.z, acc); acc = fmaf(wc.w, v2.w, acc);
        acc = fmaf(wd.x, v3.x, acc); acc = fmaf(wd.y, v3.y, acc);
        acc = fmaf(wd.z, v3.z, acc); acc = fmaf(wd.w, v3.w, acc);
        acc = warp_reduce(acc);
        if (lane == 0) s_part[warp] = acc;

        // Preload phase-3 dec_w1 slice (4 rows x 512 K = 16 float4/lane) from
        // DRAM: latency drains under the scan + flag waits.
        {
            const float4* wb4 = (const float4*)dec_w1 + ((size_t)h0 * H + kh * 512) / 4;
#pragma unroll
            for (int r = 0; r < 4; r++)
#pragma unroll
                for (int j = 0; j < 4; j++)
                    w16[r * 4 + j] = __ldg(wb4 + r * 256 + j * 32 + lane);
        }

        __syncthreads();
        if (tid < 8) {
            const int g = blockIdx.x * 8 + tid;
            const float pre = s_part[tid] + s_part[tid + 8] + dec_b0[g];
            const float uu = dec_u0[g];
            float d = 0.0f;
#pragma unroll
            for (int t = 0; t < T; t++) {
                d = fmaxf(fmaf(uu, d, pre), 0.0f);
                g_d0[t * H + g] = d;
            }
        }
        // Publish this block's chunk: all 8 channel stores done (sync), then
        // release-arrive on chunk flag (16 producers per chunk).
        __syncthreads();
        if (tid == 0) {
            __threadfence();
            atomicAdd(&g_flag[(blockIdx.x >> 4) * 32], 1u);
        }
    }

    // ---- Phase 3 (NO grid barrier): pre1[t][h] = dec_w1[h] . d0[t] + b[h].
    // 4 rows x 5 t x 512 K per warp; weights in registers. Each j consumes one
    // 128-channel chunk; wait on its flag (acquire) before loading.
    {
        const float4* d0b = (const float4*)g_d0 + tq * 5 * (H / 4) + kh * 128;

        float acc[4][5];
#pragma unroll
        for (int r = 0; r < 4; r++)
#pragma unroll
            for (int t = 0; t < 5; t++) acc[r][t] = 0.0f;

#pragma unroll
        for (int j = 0; j < 4; j++) {
            // Chunk kh*4+j: channels [ (kh*4+j)*128, +128 ). Spin until its 16
            // producer blocks have arrived (acquire orders subsequent d0 loads).
            {
                const unsigned* fl = &g_flag[(kh * 4 + j) * 32];
                while (ld_acquire(fl) < 16u) {}
            }
            const int c = j * 32 + lane;
            float4 v[5];
#pragma unroll
            for (int t = 0; t < 5; t++) v[t] = d0b[t * 256 + c];    // coherent
#pragma unroll
            for (int r = 0; r < 4; r++) {
                const float4 a = w16[r * 4 + j];
#pragma unroll
                for (int t = 0; t < 5; t++) {
                    acc[r][t] = fmaf(a.x, v[t].x, acc[r][t]);
                    acc[r][t] = fmaf(a.y, v[t].y, acc[r][t]);
                    acc[r][t] = fmaf(a.z, v[t].z, acc[r][t]);
                    acc[r][t] = fmaf(a.w, v[t].w, acc[r][t]);
                }
            }
        }
#pragma unroll
        for (int r = 0; r < 4; r++) {
#pragma unroll
            for (int t = 0; t < 5; t++) {
                acc[r][t] = warp_reduce(acc[r][t]);   // butterfly: all lanes hold sum
            }
            if (lane == r) {
#pragma unroll
                for (int t = 0; t < 5; t++)
                    s_pre[kh][rq * 4 + r][tq * 5 + t] = acc[r][t];
            }
        }
        __syncthreads();

        // dec1 scan -> s_d1 (combine K-half partials), 8 threads.
        if (tid < 8) {
            const int hh = blockIdx.x * 8 + tid;
            const float bb = dec_b1[hh], uu = dec_u1[hh];
            float d = 0.0f;
#pragma unroll
            for (int t = 0; t < T; t++) {
                d = fmaxf(fmaf(uu, d, s_pre[0][tid][t] + s_pre[1][tid][t] + bb), 0.0f);
                s_d1[tid][t] = d;
            }
        }
        __syncthreads();

        // Output projection, block-pre-reduced: 40 threads each fold this
        // block's 8 channels for one (t,k), then a single atomicAdd.
        // Wait (acquire) for block 0's out_b init first (in practice: no wait).
        if (tid < 2 * T) {
            while (ld_acquire(&g_outrdy) == 0u) {}
            const int t = tid >> 1, k = tid & 1;
            const float* owr = out_w + (size_t)k * H + blockIdx.x * 8;
            float sum = 0.0f;
#pragma unroll
            for (int ch = 0; ch < 8; ch++)
                sum = fmaf(owr[ch], s_d1[ch][t], sum);
            atomicAdd(out + tid, sum);
        }
    }
}

extern "C" void kernel_launch(void* const* d_in, const int* in_sizes, int n_in,
                              void* d_out, int out_size) {
    const float* x      = (const float*)d_in[0];
    const float* enc_w0 = (const float*)d_in[1];
    // d_in[2] = enc_u0: unused (only t=0 encoder state needed, h_{-1}=0)
    const float* enc_b0 = (const float*)d_in[3];
    const float* enc_w1 = (const float*)d_in[4];
    // d_in[5] = enc_u1: unused
    const float* enc_b1 = (const float*)d_in[6];
    const float* dec_w0 = (const float*)d_in[7];
    const float* dec_u0 = (const float*)d_in[8];
    const float* dec_b0 = (const float*)d_in[9];
    const float* dec_w1 = (const float*)d_in[10];
    const float* dec_u1 = (const float*)d_in[11];
    const float* dec_b1 = (const float*)d_in[12];
    const float* out_w  = (const float*)d_in[13];
    const float* out_b  = (const float*)d_in[14];
    float* out = (float*)d_out;

    fused_net<<<GRID, BLK>>>(x, enc_w0, enc_b0, enc_w1, enc_b1,
                             dec_w0, dec_u0, dec_b0,
                             dec_w1, dec_u1, dec_b1,
                             out_w, out_b, out);
}